// round 13
// baseline (speedup 1.0000x reference)
#include <cuda_runtime.h>
#include <cuda_bf16.h>
#include <math.h>
#include <stdint.h>

#define NTOK 2048
#define VOCAB 32000
#define KSTU 1024
#define KTEA 2048
#define IGNORE_INDEX (-100)

// int8 symmetric quantization scales (descaled exactly in fp32 epilogue)
#define S_X 20.0f
#define S_W 1100.0f
#define DESCALE (1.0f / (S_X * S_W))

// ---------------- scratch (device globals; no runtime allocation) -----------
__device__ __align__(16) int8_t g_SI[NTOK * KSTU];
__device__ __align__(16) int8_t g_TI[NTOK * KTEA];
__device__ __align__(16) int8_t g_SW[(size_t)VOCAB * KSTU];
__device__ __align__(16) int8_t g_TW[(size_t)VOCAB * KTEA];
__device__ __align__(16) __nv_bfloat16 g_LSb[(size_t)NTOK * VOCAB];
__device__ __align__(16) __nv_bfloat16 g_LTb[(size_t)NTOK * VOCAB];
__device__ float g_seS[NTOK];   // per-row sum of exp(student logit)
__device__ float g_seT[NTOK];   // per-row sum of exp(teacher logit)
__device__ int g_tgt[NTOK];
__device__ double g_hard;
__device__ double g_skl;
__device__ double g_tkl;
__device__ int g_nvalid;

// ---------------- PTX helpers ------------------------------------------------
#define CP_ASYNC_CG(dst_u32, src_ptr) \
    asm volatile("cp.async.cg.shared.global [%0], [%1], 16;\n" ::"r"(dst_u32), \
                 "l"(src_ptr))
#define CP_ASYNC_COMMIT asm volatile("cp.async.commit_group;\n")
#define CP_ASYNC_WAIT_2 asm volatile("cp.async.wait_group 2;\n" ::: "memory")
#define CP_ASYNC_WAIT_1 asm volatile("cp.async.wait_group 1;\n" ::: "memory")
#define CP_ASYNC_WAIT_0 asm volatile("cp.async.wait_group 0;\n" ::: "memory")

__device__ __forceinline__ void ldsm_x4(uint32_t& r0, uint32_t& r1, uint32_t& r2,
                                        uint32_t& r3, uint32_t addr) {
    asm volatile("ldmatrix.sync.aligned.m8n8.x4.shared.b16 {%0,%1,%2,%3}, [%4];"
                 : "=r"(r0), "=r"(r1), "=r"(r2), "=r"(r3)
                 : "r"(addr));
}

// int8 IMMA: m16n8k32, s32 accum (exact). Same operand byte layout as the
// fp8 k32 variant -> identical smem layout / ldsm addressing.
__device__ __forceinline__ void mma16832_s8(int c[4], const uint32_t a[4],
                                            const uint32_t b[2]) {
    asm("mma.sync.aligned.m16n8k32.row.col.s32.s8.s8.s32 "
        "{%0,%1,%2,%3},{%4,%5,%6,%7},{%8,%9},{%0,%1,%2,%3};"
        : "+r"(c[0]), "+r"(c[1]), "+r"(c[2]), "+r"(c[3])
        : "r"(a[0]), "r"(a[1]), "r"(a[2]), "r"(a[3]), "r"(b[0]), "r"(b[1]));
}

__device__ __forceinline__ int q8(float x, float s) {
    int v = __float2int_rn(x * s);
    return max(-127, min(127, v));
}

__device__ __forceinline__ uint32_t pack4_s8(float4 v, float s) {
    uint32_t a = (uint32_t)(uint8_t)q8(v.x, s);
    uint32_t b = (uint32_t)(uint8_t)q8(v.y, s);
    uint32_t c = (uint32_t)(uint8_t)q8(v.z, s);
    uint32_t d = (uint32_t)(uint8_t)q8(v.w, s);
    return a | (b << 8) | (c << 16) | (d << 24);
}

// ---------------- small kernels ----------------------------------------------
__global__ void zero_acc_kernel() {
    int idx = blockIdx.x * blockDim.x + threadIdx.x;
    if (idx == 0) {
        g_hard = 0.0;
        g_skl = 0.0;
        g_tkl = 0.0;
        g_nvalid = 0;
    }
    if (idx < NTOK) {
        g_seS[idx] = 0.0f;
        g_seT[idx] = 0.0f;
    }
}

// JAX silently downcasts int64->int32 unless x64 is enabled; handle both.
__global__ __launch_bounds__(1024) void tgt_cvt_kernel(const int* __restrict__ raw) {
    __shared__ int s_all64;
    int tid = threadIdx.x;
    if (tid == 0) s_all64 = 1;
    __syncthreads();
    int hw = raw[2 * tid + 1];
    if (hw != 0 && hw != -1) atomicAnd(&s_all64, 0);
    __syncthreads();
    int is64 = s_all64;
    for (int i = tid; i < NTOK; i += 1024) {
        g_tgt[i] = is64 ? raw[2 * i] : raw[i];
    }
}

// fp32 -> s8 convert. Each thread: 4 float4 loads (64B) -> one uint4 store.
__global__ void cvt_s8_kernel(const float4* __restrict__ src, int which,
                              float scale) {
    int tid = blockIdx.x * blockDim.x + threadIdx.x;
    int8_t* dstb =
        which == 0 ? g_SI : which == 1 ? g_TI : which == 2 ? g_SW : g_TW;
    uint4* dst = (uint4*)dstb;
    float4 v0 = src[4 * tid + 0];
    float4 v1 = src[4 * tid + 1];
    float4 v2 = src[4 * tid + 2];
    float4 v3 = src[4 * tid + 3];
    uint4 o;
    o.x = pack4_s8(v0, scale);
    o.y = pack4_s8(v1, scale);
    o.z = pack4_s8(v2, scale);
    o.w = pack4_s8(v3, scale);
    dst[tid] = o;
}

// ---------------- merged int8 IMMA GEMM (student + teacher) ------------------
// blocks [0,4000): student (K=1024); [4000,8000): teacher (K=2048).
// CTA tile 128(tokens) x 128(vocab), 64B K-slab per stage, 4-stage cp.async,
// ldmatrix.x4 operands. Epilogue descales to fp32 logits, stores bf16, and
// accumulates per-row sum(exp(logit)) into g_seS/g_seT.
__global__ __launch_bounds__(256, 2) void gemm_kernel() {
    const int bid = blockIdx.x;
    const bool stu = bid < 4000;
    const int K = stu ? KSTU : KTEA;
    const int NS = K / 64;
    const int8_t* __restrict__ A = stu ? g_SI : g_TI;
    const int8_t* __restrict__ B = stu ? g_SW : g_TW;
    __nv_bfloat16* __restrict__ C = stu ? g_LSb : g_LTb;
    float* __restrict__ rowsum = stu ? g_seS : g_seT;

    const int b = stu ? bid : bid - 4000;
    const int m0 = (b & 15) * 128;   // token tile (fastest -> weight reuse in L2)
    const int n0 = (b >> 4) * 128;   // vocab tile

    constexpr int LDS_T = 80;            // padded row stride in BYTES (64B data)
    constexpr int A_BYTES = 128 * LDS_T;
    constexpr int B_BYTES = 128 * LDS_T;
    constexpr int STAGE_BYTES = A_BYTES + B_BYTES;  // 20480B

    extern __shared__ uint8_t sm[];

    const int tid = threadIdx.x;
    const int lane = tid & 31;
    const int wid = tid >> 5;
    const int warp_m = wid >> 2;   // 0..1
    const int warp_n = wid & 3;    // 0..3
    const int grp = lane >> 2;     // 0..7
    const int tq = lane & 3;       // 0..3

    const uint32_t smem_u32 = (uint32_t)__cvta_generic_to_shared(sm);

    const int aoff = ((lane & 7) + ((lane >> 3) & 1) * 8) * LDS_T + (lane >> 4) * 16;
    const int boff = ((lane & 7) + ((lane >> 4) & 1) * 8) * LDS_T + ((lane >> 3) & 1) * 16;

    int acc[4][4][4];
#pragma unroll
    for (int mi = 0; mi < 4; mi++)
#pragma unroll
        for (int ni = 0; ni < 4; ni++)
#pragma unroll
            for (int r = 0; r < 4; r++) acc[mi][ni][r] = 0;

    auto load_stage = [&](int ks) {
        const int buf = ks & 3;
        const uint32_t a_base = smem_u32 + buf * STAGE_BYTES;
        const uint32_t b_base = a_base + A_BYTES;
        const int kk0 = ks * 64;
#pragma unroll
        for (int j = 0; j < 4; j++) {
            int id = tid + j * 256;       // 0..1023
            int row = (id >> 2) & 127;
            int c = id & 3;
            if (id < 512) {
                CP_ASYNC_CG(a_base + row * LDS_T + c * 16,
                            &A[(size_t)(m0 + row) * K + kk0 + c * 16]);
            } else {
                CP_ASYNC_CG(b_base + row * LDS_T + c * 16,
                            &B[(size_t)(n0 + row) * K + kk0 + c * 16]);
            }
        }
    };

    // NS >= 16 always
    load_stage(0);
    CP_ASYNC_COMMIT;
    load_stage(1);
    CP_ASYNC_COMMIT;
    load_stage(2);
    CP_ASYNC_COMMIT;

    for (int ks = 0; ks < NS; ks++) {
        const int buf = ks & 3;
        const int rem = NS - 1 - ks;
        if (rem >= 2) { CP_ASYNC_WAIT_2; }
        else if (rem == 1) { CP_ASYNC_WAIT_1; }
        else { CP_ASYNC_WAIT_0; }
        __syncthreads();

        if (ks + 3 < NS) {
            load_stage(ks + 3);
            CP_ASYNC_COMMIT;
        }

        const uint32_t as = smem_u32 + buf * STAGE_BYTES;
        const uint32_t bs = as + A_BYTES;

#pragma unroll
        for (int kk = 0; kk < 2; kk++) {
            const int kb = kk * 32;
            uint32_t a[4][4], bfr[4][2];
#pragma unroll
            for (int mi = 0; mi < 4; mi++) {
                uint32_t addr = as + (warp_m * 64 + mi * 16) * LDS_T + kb + aoff;
                ldsm_x4(a[mi][0], a[mi][1], a[mi][2], a[mi][3], addr);
            }
#pragma unroll
            for (int nj = 0; nj < 2; nj++) {
                uint32_t addr = bs + (warp_n * 32 + nj * 16) * LDS_T + kb + boff;
                ldsm_x4(bfr[2 * nj][0], bfr[2 * nj][1], bfr[2 * nj + 1][0],
                        bfr[2 * nj + 1][1], addr);
            }
#pragma unroll
            for (int mi = 0; mi < 4; mi++)
#pragma unroll
                for (int ni = 0; ni < 4; ni++)
                    mma16832_s8(acc[mi][ni], a[mi], bfr[ni]);
        }
    }

    // epilogue: descale s32 -> fp32 logits, store bf16, accumulate per-row
    // sumexp partials (quad-shfl reduce -> one atomicAdd per row per warp).
#pragma unroll
    for (int mi = 0; mi < 4; mi++) {
        float rs_lo = 0.0f, rs_hi = 0.0f;
#pragma unroll
        for (int ni = 0; ni < 4; ni++) {
            int row = m0 + warp_m * 64 + mi * 16 + grp;
            int col = n0 + warp_n * 32 + ni * 8 + tq * 2;
            float l0 = (float)acc[mi][ni][0] * DESCALE;
            float l1 = (float)acc[mi][ni][1] * DESCALE;
            float l2 = (float)acc[mi][ni][2] * DESCALE;
            float l3 = (float)acc[mi][ni][3] * DESCALE;
            *(__nv_bfloat162*)&C[(size_t)row * VOCAB + col] =
                __floats2bfloat162_rn(l0, l1);
            *(__nv_bfloat162*)&C[(size_t)(row + 8) * VOCAB + col] =
                __floats2bfloat162_rn(l2, l3);
            rs_lo += __expf(l0) + __expf(l1);
            rs_hi += __expf(l2) + __expf(l3);
        }
        rs_lo += __shfl_xor_sync(0xFFFFFFFFu, rs_lo, 1);
        rs_lo += __shfl_xor_sync(0xFFFFFFFFu, rs_lo, 2);
        rs_hi += __shfl_xor_sync(0xFFFFFFFFu, rs_hi, 1);
        rs_hi += __shfl_xor_sync(0xFFFFFFFFu, rs_hi, 2);
        if (tq == 0) {
            int row = m0 + warp_m * 64 + mi * 16 + grp;
            atomicAdd(&rowsum[row], rs_lo);
            atomicAdd(&rowsum[row + 8], rs_hi);
        }
    }
}

// -------- single-pass stats: lse from accumulated sumexp; JSD + hard CE -----
__global__ __launch_bounds__(256) void stats_kernel() {
    const int row = blockIdx.x;
    const __nv_bfloat16* __restrict__ s = g_LSb + (size_t)row * VOCAB;
    const __nv_bfloat16* __restrict__ t = g_LTb + (size_t)row * VOCAB;
    const int tid = threadIdx.x;
    constexpr int NCHUNK = VOCAB / 8;

    const float lseS = logf(g_seS[row]);
    const float lseT = logf(g_seT[row]);

    float skl = 0.0f, tkl = 0.0f;
    for (int c = tid; c < NCHUNK; c += 256) {
        uint4 vs = *(const uint4*)&s[c * 8];
        uint4 vt = *(const uint4*)&t[c * 8];
        const __nv_bfloat16* es = (const __nv_bfloat16*)&vs;
        const __nv_bfloat16* et = (const __nv_bfloat16*)&vt;
#pragma unroll
        for (int j = 0; j < 8; j++) {
            float lps = __bfloat162float(es[j]) - lseS;
            float lpt = __bfloat162float(et[j]) - lseT;
            float sp = __expf(lps);
            float tp = __expf(lpt);
            float lm = __logf(0.5f * (sp + tp));
            skl += sp * (lps - lm);
            tkl += tp * (lpt - lm);
        }
    }

    __shared__ float shsS[256], shsT[256];
    shsS[tid] = skl;
    shsT[tid] = tkl;
    __syncthreads();
    for (int off = 128; off > 0; off >>= 1) {
        if (tid < off) {
            shsS[tid] += shsS[tid + off];
            shsT[tid] += shsT[tid + off];
        }
        __syncthreads();
    }
    if (tid == 0) {
        atomicAdd(&g_skl, (double)shsS[0]);
        atomicAdd(&g_tkl, (double)shsT[0]);
        int tg = g_tgt[row];
        if (tg != IGNORE_INDEX) {
            float nll = lseS - __bfloat162float(s[tg]);
            atomicAdd(&g_hard, (double)nll);
            atomicAdd(&g_nvalid, 1);
        }
    }
}

// ---------------- finalize ---------------------------------------------------
__global__ void finalize_kernel(float* out) {
    int nv = g_nvalid > 0 ? g_nvalid : 1;
    double hard = g_hard / (double)nv;
    double jsd = 0.5 * (g_skl + g_tkl) / (double)NTOK;
    out[0] = (float)(0.5 * hard + 0.5 * jsd);
}

// ---------------- launch ------------------------------------------------------
// Launch order puts the GEMM at index 5: the harness's fixed `ncu -s 5 -c 1`
// capture then profiles the GEMM instead of a cvt kernel.
extern "C" void kernel_launch(void* const* d_in, const int* in_sizes, int n_in,
                              void* d_out, int out_size) {
    const float* si = (const float*)d_in[0];      // (N, H/2)
    const float* ti = (const float*)d_in[1];      // (N, H)
    const float* sw = (const float*)d_in[2];      // (V, H/2)
    const float* tw = (const float*)d_in[3];      // (V, H)
    const int* tgt_raw = (const int*)d_in[4];     // int32 or int64 (detected)
    float* out = (float*)d_out;

    const int SMEM_BYTES = 4 * 20480;  // 4-stage pipeline, 80KB
    cudaFuncSetAttribute(gemm_kernel,
                         cudaFuncAttributeMaxDynamicSharedMemorySize, SMEM_BYTES);

    // launches 0-3: fp32 -> s8 (16 elements per thread)
    cvt_s8_kernel<<<NTOK * KSTU / 16 / 256, 256>>>((const float4*)si, 0, S_X);
    cvt_s8_kernel<<<NTOK * KTEA / 16 / 256, 256>>>((const float4*)ti, 1, S_X);
    cvt_s8_kernel<<<VOCAB * KSTU / 16 / 256, 256>>>((const float4*)sw, 2, S_W);
    cvt_s8_kernel<<<VOCAB * KTEA / 16 / 256, 256>>>((const float4*)tw, 3, S_W);

    zero_acc_kernel<<<2, 1024>>>();  // launch 4 (must precede gemm atomics)

    gemm_kernel<<<8000, 256, SMEM_BYTES>>>();  // launch 5 -> ncu profiles this

    tgt_cvt_kernel<<<1, 1024>>>(tgt_raw);      // launch 6 (before stats)
    stats_kernel<<<NTOK, 256>>>();
    finalize_kernel<<<1, 1>>>(out);
}

// round 14
// speedup vs baseline: 2.3679x; 2.3679x over previous
#include <cuda_runtime.h>
#include <cuda_bf16.h>
#include <cuda_fp16.h>
#include <math.h>
#include <stdint.h>

#define NTOK 2048
#define VOCAB 32000
#define KSTU 1024
#define KTEA 2048
#define IGNORE_INDEX (-100)

// Weight pre-scale for e4m3 range (exact power of two; undone in epilogue).
#define WSCALE 64.0f
#define WSCALE_INV 0.015625f

// ---------------- scratch (device globals; no runtime allocation) -----------
__device__ __align__(16) uint8_t g_SI[NTOK * KSTU];
__device__ __align__(16) uint8_t g_TI[NTOK * KTEA];
__device__ __align__(16) uint8_t g_SW[(size_t)VOCAB * KSTU];
__device__ __align__(16) uint8_t g_TW[(size_t)VOCAB * KTEA];
__device__ __align__(16) __nv_bfloat16 g_LSb[(size_t)NTOK * VOCAB];
__device__ __align__(16) __nv_bfloat16 g_LTb[(size_t)NTOK * VOCAB];
__device__ float g_seS[NTOK];   // per-row sum of exp(student logit)
__device__ float g_seT[NTOK];   // per-row sum of exp(teacher logit)
__device__ int g_tgt[NTOK];
__device__ double g_hard;
__device__ double g_skl;
__device__ double g_tkl;
__device__ int g_nvalid;

// ---------------- PTX helpers ------------------------------------------------
#define CP_ASYNC_CG(dst_u32, src_ptr) \
    asm volatile("cp.async.cg.shared.global [%0], [%1], 16;\n" ::"r"(dst_u32), \
                 "l"(src_ptr))
#define CP_ASYNC_COMMIT asm volatile("cp.async.commit_group;\n")
#define CP_ASYNC_WAIT_2 asm volatile("cp.async.wait_group 2;\n" ::: "memory")
#define CP_ASYNC_WAIT_1 asm volatile("cp.async.wait_group 1;\n" ::: "memory")
#define CP_ASYNC_WAIT_0 asm volatile("cp.async.wait_group 0;\n" ::: "memory")

__device__ __forceinline__ void ldsm_x4(uint32_t& r0, uint32_t& r1, uint32_t& r2,
                                        uint32_t& r3, uint32_t addr) {
    asm volatile("ldmatrix.sync.aligned.m8n8.x4.shared.b16 {%0,%1,%2,%3}, [%4];"
                 : "=r"(r0), "=r"(r1), "=r"(r2), "=r"(r3)
                 : "r"(addr));
}

// fp8 e4m3 MMA with f16 accumulators: m16n8k32. D/C are 2 b32 regs
// (4 f16 per thread). Operand layout identical to the f32-accum variant.
__device__ __forceinline__ void mma16832_fp8_f16acc(uint32_t c[2],
                                                    const uint32_t a[4],
                                                    const uint32_t b[2]) {
    asm("mma.sync.aligned.m16n8k32.row.col.f16.e4m3.e4m3.f16 "
        "{%0,%1},{%2,%3,%4,%5},{%6,%7},{%0,%1};"
        : "+r"(c[0]), "+r"(c[1])
        : "r"(a[0]), "r"(a[1]), "r"(a[2]), "r"(a[3]), "r"(b[0]), "r"(b[1]));
}

__device__ __forceinline__ uint32_t pack4_e4m3(float4 v, float s) {
    uint16_t lo, hi;
    asm("cvt.rn.satfinite.e4m3x2.f32 %0, %1, %2;"
        : "=h"(lo) : "f"(v.y * s), "f"(v.x * s));
    asm("cvt.rn.satfinite.e4m3x2.f32 %0, %1, %2;"
        : "=h"(hi) : "f"(v.w * s), "f"(v.z * s));
    return (uint32_t)lo | ((uint32_t)hi << 16);
}

// ---------------- small kernels ----------------------------------------------
__global__ void zero_acc_kernel() {
    int idx = blockIdx.x * blockDim.x + threadIdx.x;
    if (idx == 0) {
        g_hard = 0.0;
        g_skl = 0.0;
        g_tkl = 0.0;
        g_nvalid = 0;
    }
    if (idx < NTOK) {
        g_seS[idx] = 0.0f;
        g_seT[idx] = 0.0f;
    }
}

// JAX silently downcasts int64->int32 unless x64 is enabled; handle both.
__global__ __launch_bounds__(1024) void tgt_cvt_kernel(const int* __restrict__ raw) {
    __shared__ int s_all64;
    int tid = threadIdx.x;
    if (tid == 0) s_all64 = 1;
    __syncthreads();
    int hw = raw[2 * tid + 1];
    if (hw != 0 && hw != -1) atomicAnd(&s_all64, 0);
    __syncthreads();
    int is64 = s_all64;
    for (int i = tid; i < NTOK; i += 1024) {
        g_tgt[i] = is64 ? raw[2 * i] : raw[i];
    }
}

// fp32 -> e4m3 convert. Each thread: 4 float4 loads (64B) -> one uint4 store.
__global__ void cvt_fp8_kernel(const float4* __restrict__ src, int which,
                               float scale) {
    int tid = blockIdx.x * blockDim.x + threadIdx.x;
    uint8_t* dstb =
        which == 0 ? g_SI : which == 1 ? g_TI : which == 2 ? g_SW : g_TW;
    uint4* dst = (uint4*)dstb;
    float4 v0 = src[4 * tid + 0];
    float4 v1 = src[4 * tid + 1];
    float4 v2 = src[4 * tid + 2];
    float4 v3 = src[4 * tid + 3];
    uint4 o;
    o.x = pack4_e4m3(v0, scale);
    o.y = pack4_e4m3(v1, scale);
    o.z = pack4_e4m3(v2, scale);
    o.w = pack4_e4m3(v3, scale);
    dst[tid] = o;
}

// ---------------- merged fp8 mma GEMM (student + teacher) --------------------
// blocks [0,4000): student (K=1024); [4000,8000): teacher (K=2048).
// CTA tile 128(tokens) x 128(vocab), 64B K-slab per stage, 4-stage cp.async,
// ldmatrix.x4 operands, f16 accumulators (halved acc register file).
// Epilogue descales, stores bf16 logits, accumulates per-row sumexp.
__global__ __launch_bounds__(256, 2) void gemm_kernel() {
    const int bid = blockIdx.x;
    const bool stu = bid < 4000;
    const int K = stu ? KSTU : KTEA;
    const int NS = K / 64;
    const uint8_t* __restrict__ A = stu ? g_SI : g_TI;
    const uint8_t* __restrict__ B = stu ? g_SW : g_TW;
    __nv_bfloat16* __restrict__ C = stu ? g_LSb : g_LTb;
    float* __restrict__ rowsum = stu ? g_seS : g_seT;

    const int b = stu ? bid : bid - 4000;
    const int m0 = (b & 15) * 128;   // token tile (fastest -> weight reuse in L2)
    const int n0 = (b >> 4) * 128;   // vocab tile

    constexpr int LDS_T = 80;            // padded row stride in BYTES (64B data)
    constexpr int A_BYTES = 128 * LDS_T;
    constexpr int B_BYTES = 128 * LDS_T;
    constexpr int STAGE_BYTES = A_BYTES + B_BYTES;  // 20480B

    extern __shared__ uint8_t sm[];

    const int tid = threadIdx.x;
    const int lane = tid & 31;
    const int wid = tid >> 5;
    const int warp_m = wid >> 2;   // 0..1
    const int warp_n = wid & 3;    // 0..3
    const int grp = lane >> 2;     // 0..7
    const int tq = lane & 3;       // 0..3

    const uint32_t smem_u32 = (uint32_t)__cvta_generic_to_shared(sm);

    const int aoff = ((lane & 7) + ((lane >> 3) & 1) * 8) * LDS_T + (lane >> 4) * 16;
    const int boff = ((lane & 7) + ((lane >> 4) & 1) * 8) * LDS_T + ((lane >> 3) & 1) * 16;

    uint32_t acc[4][4][2];  // f16x2 accumulators
#pragma unroll
    for (int mi = 0; mi < 4; mi++)
#pragma unroll
        for (int ni = 0; ni < 4; ni++) {
            acc[mi][ni][0] = 0u;
            acc[mi][ni][1] = 0u;
        }

    auto load_stage = [&](int ks) {
        const int buf = ks & 3;
        const uint32_t a_base = smem_u32 + buf * STAGE_BYTES;
        const uint32_t b_base = a_base + A_BYTES;
        const int kk0 = ks * 64;
#pragma unroll
        for (int j = 0; j < 4; j++) {
            int id = tid + j * 256;       // 0..1023
            int row = (id >> 2) & 127;
            int c = id & 3;
            if (id < 512) {
                CP_ASYNC_CG(a_base + row * LDS_T + c * 16,
                            &A[(size_t)(m0 + row) * K + kk0 + c * 16]);
            } else {
                CP_ASYNC_CG(b_base + row * LDS_T + c * 16,
                            &B[(size_t)(n0 + row) * K + kk0 + c * 16]);
            }
        }
    };

    // NS >= 16 always
    load_stage(0);
    CP_ASYNC_COMMIT;
    load_stage(1);
    CP_ASYNC_COMMIT;
    load_stage(2);
    CP_ASYNC_COMMIT;

    for (int ks = 0; ks < NS; ks++) {
        const int buf = ks & 3;
        const int rem = NS - 1 - ks;
        if (rem >= 2) { CP_ASYNC_WAIT_2; }
        else if (rem == 1) { CP_ASYNC_WAIT_1; }
        else { CP_ASYNC_WAIT_0; }
        __syncthreads();

        if (ks + 3 < NS) {
            load_stage(ks + 3);
            CP_ASYNC_COMMIT;
        }

        const uint32_t as = smem_u32 + buf * STAGE_BYTES;
        const uint32_t bs = as + A_BYTES;

#pragma unroll
        for (int kk = 0; kk < 2; kk++) {
            const int kb = kk * 32;
            uint32_t a[4][4], bfr[4][2];
#pragma unroll
            for (int mi = 0; mi < 4; mi++) {
                uint32_t addr = as + (warp_m * 64 + mi * 16) * LDS_T + kb + aoff;
                ldsm_x4(a[mi][0], a[mi][1], a[mi][2], a[mi][3], addr);
            }
#pragma unroll
            for (int nj = 0; nj < 2; nj++) {
                uint32_t addr = bs + (warp_n * 32 + nj * 16) * LDS_T + kb + boff;
                ldsm_x4(bfr[2 * nj][0], bfr[2 * nj][1], bfr[2 * nj + 1][0],
                        bfr[2 * nj + 1][1], addr);
            }
#pragma unroll
            for (int mi = 0; mi < 4; mi++)
#pragma unroll
                for (int ni = 0; ni < 4; ni++)
                    mma16832_fp8_f16acc(acc[mi][ni], a[mi], bfr[ni]);
        }
    }

    // epilogue: f16 acc -> fp32, undo weight pre-scale, store bf16 logits,
    // accumulate per-row sumexp partials (quad-shfl -> atomicAdd).
#pragma unroll
    for (int mi = 0; mi < 4; mi++) {
        float rs_lo = 0.0f, rs_hi = 0.0f;
#pragma unroll
        for (int ni = 0; ni < 4; ni++) {
            int row = m0 + warp_m * 64 + mi * 16 + grp;
            int col = n0 + warp_n * 32 + ni * 8 + tq * 2;
            __half2 h01 = *(__half2*)&acc[mi][ni][0];
            __half2 h23 = *(__half2*)&acc[mi][ni][1];
            float l0 = __low2float(h01) * WSCALE_INV;
            float l1 = __high2float(h01) * WSCALE_INV;
            float l2 = __low2float(h23) * WSCALE_INV;
            float l3 = __high2float(h23) * WSCALE_INV;
            *(__nv_bfloat162*)&C[(size_t)row * VOCAB + col] =
                __floats2bfloat162_rn(l0, l1);
            *(__nv_bfloat162*)&C[(size_t)(row + 8) * VOCAB + col] =
                __floats2bfloat162_rn(l2, l3);
            rs_lo += __expf(l0) + __expf(l1);
            rs_hi += __expf(l2) + __expf(l3);
        }
        rs_lo += __shfl_xor_sync(0xFFFFFFFFu, rs_lo, 1);
        rs_lo += __shfl_xor_sync(0xFFFFFFFFu, rs_lo, 2);
        rs_hi += __shfl_xor_sync(0xFFFFFFFFu, rs_hi, 1);
        rs_hi += __shfl_xor_sync(0xFFFFFFFFu, rs_hi, 2);
        if (tq == 0) {
            int row = m0 + warp_m * 64 + mi * 16 + grp;
            atomicAdd(&rowsum[row], rs_lo);
            atomicAdd(&rowsum[row + 8], rs_hi);
        }
    }
}

// -------- single-pass stats: lse from accumulated sumexp; JSD + hard CE -----
__global__ __launch_bounds__(256) void stats_kernel() {
    const int row = blockIdx.x;
    const __nv_bfloat16* __restrict__ s = g_LSb + (size_t)row * VOCAB;
    const __nv_bfloat16* __restrict__ t = g_LTb + (size_t)row * VOCAB;
    const int tid = threadIdx.x;
    constexpr int NCHUNK = VOCAB / 8;

    const float lseS = logf(g_seS[row]);
    const float lseT = logf(g_seT[row]);

    float skl = 0.0f, tkl = 0.0f;
    for (int c = tid; c < NCHUNK; c += 256) {
        uint4 vs = *(const uint4*)&s[c * 8];
        uint4 vt = *(const uint4*)&t[c * 8];
        const __nv_bfloat16* es = (const __nv_bfloat16*)&vs;
        const __nv_bfloat16* et = (const __nv_bfloat16*)&vt;
#pragma unroll
        for (int j = 0; j < 8; j++) {
            float lps = __bfloat162float(es[j]) - lseS;
            float lpt = __bfloat162float(et[j]) - lseT;
            float sp = __expf(lps);
            float tp = __expf(lpt);
            float lm = __logf(0.5f * (sp + tp));
            skl += sp * (lps - lm);
            tkl += tp * (lpt - lm);
        }
    }

    __shared__ float shsS[256], shsT[256];
    shsS[tid] = skl;
    shsT[tid] = tkl;
    __syncthreads();
    for (int off = 128; off > 0; off >>= 1) {
        if (tid < off) {
            shsS[tid] += shsS[tid + off];
            shsT[tid] += shsT[tid + off];
        }
        __syncthreads();
    }
    if (tid == 0) {
        atomicAdd(&g_skl, (double)shsS[0]);
        atomicAdd(&g_tkl, (double)shsT[0]);
        int tg = g_tgt[row];
        if (tg != IGNORE_INDEX) {
            float nll = lseS - __bfloat162float(s[tg]);
            atomicAdd(&g_hard, (double)nll);
            atomicAdd(&g_nvalid, 1);
        }
    }
}

// ---------------- finalize ---------------------------------------------------
__global__ void finalize_kernel(float* out) {
    int nv = g_nvalid > 0 ? g_nvalid : 1;
    double hard = g_hard / (double)nv;
    double jsd = 0.5 * (g_skl + g_tkl) / (double)NTOK;
    out[0] = (float)(0.5 * hard + 0.5 * jsd);
}

// ---------------- launch ------------------------------------------------------
extern "C" void kernel_launch(void* const* d_in, const int* in_sizes, int n_in,
                              void* d_out, int out_size) {
    const float* si = (const float*)d_in[0];      // (N, H/2)
    const float* ti = (const float*)d_in[1];      // (N, H)
    const float* sw = (const float*)d_in[2];      // (V, H/2)
    const float* tw = (const float*)d_in[3];      // (V, H)
    const int* tgt_raw = (const int*)d_in[4];     // int32 or int64 (detected)
    float* out = (float*)d_out;

    const int SMEM_BYTES = 4 * 20480;  // 4-stage pipeline, 80KB
    cudaFuncSetAttribute(gemm_kernel,
                         cudaFuncAttributeMaxDynamicSharedMemorySize, SMEM_BYTES);

    // fp32 -> e4m3 (16 elements per thread)
    cvt_fp8_kernel<<<NTOK * KSTU / 16 / 256, 256>>>((const float4*)si, 0, 1.0f);
    cvt_fp8_kernel<<<NTOK * KTEA / 16 / 256, 256>>>((const float4*)ti, 1, 1.0f);
    cvt_fp8_kernel<<<VOCAB * KSTU / 16 / 256, 256>>>((const float4*)sw, 2, WSCALE);
    cvt_fp8_kernel<<<VOCAB * KTEA / 16 / 256, 256>>>((const float4*)tw, 3, WSCALE);

    zero_acc_kernel<<<2, 1024>>>();  // must precede gemm epilogue atomics

    gemm_kernel<<<8000, 256, SMEM_BYTES>>>();  // student [0,4000) + teacher [4000,8000)

    tgt_cvt_kernel<<<1, 1024>>>(tgt_raw);      // before stats
    stats_kernel<<<NTOK, 256>>>();
    finalize_kernel<<<1, 1>>>(out);
}

// round 15
// speedup vs baseline: 2.3768x; 1.0038x over previous
#include <cuda_runtime.h>
#include <cuda_bf16.h>
#include <cuda_fp16.h>
#include <math.h>
#include <stdint.h>

#define NTOK 2048
#define VOCAB 32000
#define KSTU 1024
#define KTEA 2048
#define IGNORE_INDEX (-100)

// Weight pre-scale for e4m3 range (exact power of two; undone in epilogue).
#define WSCALE 64.0f
#define WSCALE_INV 0.015625f

// ---------------- scratch (device globals; no runtime allocation) -----------
__device__ __align__(16) uint8_t g_SI[NTOK * KSTU];
__device__ __align__(16) uint8_t g_TI[NTOK * KTEA];
__device__ __align__(16) uint8_t g_SW[(size_t)VOCAB * KSTU];
__device__ __align__(16) uint8_t g_TW[(size_t)VOCAB * KTEA];
__device__ __align__(16) __nv_bfloat16 g_LSb[(size_t)NTOK * VOCAB];
__device__ __align__(16) __nv_bfloat16 g_LTb[(size_t)NTOK * VOCAB];
__device__ float g_seS[NTOK];   // per-row sum of exp(student logit)
__device__ float g_seT[NTOK];   // per-row sum of exp(teacher logit)
__device__ int g_tgt[NTOK];
__device__ double g_hard;
__device__ double g_skl;
__device__ double g_tkl;
__device__ int g_nvalid;

// ---------------- PTX helpers ------------------------------------------------
#define CP_ASYNC_CG(dst_u32, src_ptr) \
    asm volatile("cp.async.cg.shared.global [%0], [%1], 16;\n" ::"r"(dst_u32), \
                 "l"(src_ptr))
#define CP_ASYNC_COMMIT asm volatile("cp.async.commit_group;\n")
#define CP_ASYNC_WAIT_1 asm volatile("cp.async.wait_group 1;\n" ::: "memory")
#define CP_ASYNC_WAIT_0 asm volatile("cp.async.wait_group 0;\n" ::: "memory")

__device__ __forceinline__ void ldsm_x4(uint32_t& r0, uint32_t& r1, uint32_t& r2,
                                        uint32_t& r3, uint32_t addr) {
    asm volatile("ldmatrix.sync.aligned.m8n8.x4.shared.b16 {%0,%1,%2,%3}, [%4];"
                 : "=r"(r0), "=r"(r1), "=r"(r2), "=r"(r3)
                 : "r"(addr));
}

// fp8 e4m3 MMA with f16 accumulators: m16n8k32. D/C are 2 b32 regs.
__device__ __forceinline__ void mma16832_fp8_f16acc(uint32_t c[2],
                                                    const uint32_t a[4],
                                                    const uint32_t b[2]) {
    asm("mma.sync.aligned.m16n8k32.row.col.f16.e4m3.e4m3.f16 "
        "{%0,%1},{%2,%3,%4,%5},{%6,%7},{%0,%1};"
        : "+r"(c[0]), "+r"(c[1])
        : "r"(a[0]), "r"(a[1]), "r"(a[2]), "r"(a[3]), "r"(b[0]), "r"(b[1]));
}

__device__ __forceinline__ uint32_t pack4_e4m3(float4 v, float s) {
    uint16_t lo, hi;
    asm("cvt.rn.satfinite.e4m3x2.f32 %0, %1, %2;"
        : "=h"(lo) : "f"(v.y * s), "f"(v.x * s));
    asm("cvt.rn.satfinite.e4m3x2.f32 %0, %1, %2;"
        : "=h"(hi) : "f"(v.w * s), "f"(v.z * s));
    return (uint32_t)lo | ((uint32_t)hi << 16);
}

// ---------------- small kernels ----------------------------------------------
__global__ void zero_acc_kernel() {
    int idx = blockIdx.x * blockDim.x + threadIdx.x;
    if (idx == 0) {
        g_hard = 0.0;
        g_skl = 0.0;
        g_tkl = 0.0;
        g_nvalid = 0;
    }
    if (idx < NTOK) {
        g_seS[idx] = 0.0f;
        g_seT[idx] = 0.0f;
    }
}

// JAX silently downcasts int64->int32 unless x64 is enabled; handle both.
__global__ __launch_bounds__(1024) void tgt_cvt_kernel(const int* __restrict__ raw) {
    __shared__ int s_all64;
    int tid = threadIdx.x;
    if (tid == 0) s_all64 = 1;
    __syncthreads();
    int hw = raw[2 * tid + 1];
    if (hw != 0 && hw != -1) atomicAnd(&s_all64, 0);
    __syncthreads();
    int is64 = s_all64;
    for (int i = tid; i < NTOK; i += 1024) {
        g_tgt[i] = is64 ? raw[2 * i] : raw[i];
    }
}

// fp32 -> e4m3 convert. Each thread: 4 float4 loads (64B) -> one uint4 store.
__global__ void cvt_fp8_kernel(const float4* __restrict__ src, int which,
                               float scale) {
    int tid = blockIdx.x * blockDim.x + threadIdx.x;
    uint8_t* dstb =
        which == 0 ? g_SI : which == 1 ? g_TI : which == 2 ? g_SW : g_TW;
    uint4* dst = (uint4*)dstb;
    float4 v0 = src[4 * tid + 0];
    float4 v1 = src[4 * tid + 1];
    float4 v2 = src[4 * tid + 2];
    float4 v3 = src[4 * tid + 3];
    uint4 o;
    o.x = pack4_e4m3(v0, scale);
    o.y = pack4_e4m3(v1, scale);
    o.z = pack4_e4m3(v2, scale);
    o.w = pack4_e4m3(v3, scale);
    dst[tid] = o;
}

// ---------------- merged fp8 mma GEMM (student + teacher) --------------------
// blocks [0,4000): student (K=1024); [4000,8000): teacher (K=2048).
// CTA tile 128(tokens) x 128(vocab), 64B K-slab per stage, 3-stage cp.async,
// ldmatrix.x4 operands, f16 accumulators.
// 3-stage (60KB smem) + __launch_bounds__(256,3): 3 CTAs/SM = 24 warps/SM
// for latency hiding (R13 showed the GEMM is issue/latency-limited, not
// tensor-pipe-saturated). Epilogue descales, stores bf16, accumulates sumexp.
__global__ __launch_bounds__(256, 3) void gemm_kernel() {
    const int bid = blockIdx.x;
    const bool stu = bid < 4000;
    const int K = stu ? KSTU : KTEA;
    const int NS = K / 64;
    const uint8_t* __restrict__ A = stu ? g_SI : g_TI;
    const uint8_t* __restrict__ B = stu ? g_SW : g_TW;
    __nv_bfloat16* __restrict__ C = stu ? g_LSb : g_LTb;
    float* __restrict__ rowsum = stu ? g_seS : g_seT;

    const int b = stu ? bid : bid - 4000;
    const int m0 = (b & 15) * 128;   // token tile (fastest -> weight reuse in L2)
    const int n0 = (b >> 4) * 128;   // vocab tile

    constexpr int LDS_T = 80;            // padded row stride in BYTES (64B data)
    constexpr int A_BYTES = 128 * LDS_T;
    constexpr int B_BYTES = 128 * LDS_T;
    constexpr int STAGE_BYTES = A_BYTES + B_BYTES;  // 20480B

    extern __shared__ uint8_t sm[];

    const int tid = threadIdx.x;
    const int lane = tid & 31;
    const int wid = tid >> 5;
    const int warp_m = wid >> 2;   // 0..1
    const int warp_n = wid & 3;    // 0..3
    const int grp = lane >> 2;     // 0..7
    const int tq = lane & 3;       // 0..3

    const uint32_t smem_u32 = (uint32_t)__cvta_generic_to_shared(sm);

    const int aoff = ((lane & 7) + ((lane >> 3) & 1) * 8) * LDS_T + (lane >> 4) * 16;
    const int boff = ((lane & 7) + ((lane >> 4) & 1) * 8) * LDS_T + ((lane >> 3) & 1) * 16;

    uint32_t acc[4][4][2];  // f16x2 accumulators
#pragma unroll
    for (int mi = 0; mi < 4; mi++)
#pragma unroll
        for (int ni = 0; ni < 4; ni++) {
            acc[mi][ni][0] = 0u;
            acc[mi][ni][1] = 0u;
        }

    auto load_stage = [&](int ks, int buf) {
        const uint32_t a_base = smem_u32 + buf * STAGE_BYTES;
        const uint32_t b_base = a_base + A_BYTES;
        const int kk0 = ks * 64;
#pragma unroll
        for (int j = 0; j < 4; j++) {
            int id = tid + j * 256;       // 0..1023
            int row = (id >> 2) & 127;
            int c = id & 3;
            if (id < 512) {
                CP_ASYNC_CG(a_base + row * LDS_T + c * 16,
                            &A[(size_t)(m0 + row) * K + kk0 + c * 16]);
            } else {
                CP_ASYNC_CG(b_base + row * LDS_T + c * 16,
                            &B[(size_t)(n0 + row) * K + kk0 + c * 16]);
            }
        }
    };

    // NS >= 16 always; 3-buffer ring
    load_stage(0, 0);
    CP_ASYNC_COMMIT;
    load_stage(1, 1);
    CP_ASYNC_COMMIT;

    int buf = 0;
    for (int ks = 0; ks < NS; ks++) {
        if (ks + 1 < NS) { CP_ASYNC_WAIT_1; }
        else { CP_ASYNC_WAIT_0; }
        __syncthreads();  // stage ks visible; all warps done with buffer of ks-1

        if (ks + 2 < NS) {
            int nbuf = buf + 2;
            if (nbuf >= 3) nbuf -= 3;
            load_stage(ks + 2, nbuf);  // overwrites stage ks-1's buffer (safe)
            CP_ASYNC_COMMIT;
        }

        const uint32_t as = smem_u32 + buf * STAGE_BYTES;
        const uint32_t bs = as + A_BYTES;

#pragma unroll
        for (int kk = 0; kk < 2; kk++) {
            const int kb = kk * 32;
            uint32_t a[4][4], bfr[4][2];
#pragma unroll
            for (int mi = 0; mi < 4; mi++) {
                uint32_t addr = as + (warp_m * 64 + mi * 16) * LDS_T + kb + aoff;
                ldsm_x4(a[mi][0], a[mi][1], a[mi][2], a[mi][3], addr);
            }
#pragma unroll
            for (int nj = 0; nj < 2; nj++) {
                uint32_t addr = bs + (warp_n * 32 + nj * 16) * LDS_T + kb + boff;
                ldsm_x4(bfr[2 * nj][0], bfr[2 * nj][1], bfr[2 * nj + 1][0],
                        bfr[2 * nj + 1][1], addr);
            }
#pragma unroll
            for (int mi = 0; mi < 4; mi++)
#pragma unroll
                for (int ni = 0; ni < 4; ni++)
                    mma16832_fp8_f16acc(acc[mi][ni], a[mi], bfr[ni]);
        }

        if (++buf == 3) buf = 0;
    }

    // epilogue: f16 acc -> fp32, undo weight pre-scale, store bf16 logits,
    // accumulate per-row sumexp partials (quad-shfl -> atomicAdd).
#pragma unroll
    for (int mi = 0; mi < 4; mi++) {
        float rs_lo = 0.0f, rs_hi = 0.0f;
#pragma unroll
        for (int ni = 0; ni < 4; ni++) {
            int row = m0 + warp_m * 64 + mi * 16 + grp;
            int col = n0 + warp_n * 32 + ni * 8 + tq * 2;
            __half2 h01 = *(__half2*)&acc[mi][ni][0];
            __half2 h23 = *(__half2*)&acc[mi][ni][1];
            float l0 = __low2float(h01) * WSCALE_INV;
            float l1 = __high2float(h01) * WSCALE_INV;
            float l2 = __low2float(h23) * WSCALE_INV;
            float l3 = __high2float(h23) * WSCALE_INV;
            *(__nv_bfloat162*)&C[(size_t)row * VOCAB + col] =
                __floats2bfloat162_rn(l0, l1);
            *(__nv_bfloat162*)&C[(size_t)(row + 8) * VOCAB + col] =
                __floats2bfloat162_rn(l2, l3);
            rs_lo += __expf(l0) + __expf(l1);
            rs_hi += __expf(l2) + __expf(l3);
        }
        rs_lo += __shfl_xor_sync(0xFFFFFFFFu, rs_lo, 1);
        rs_lo += __shfl_xor_sync(0xFFFFFFFFu, rs_lo, 2);
        rs_hi += __shfl_xor_sync(0xFFFFFFFFu, rs_hi, 1);
        rs_hi += __shfl_xor_sync(0xFFFFFFFFu, rs_hi, 2);
        if (tq == 0) {
            int row = m0 + warp_m * 64 + mi * 16 + grp;
            atomicAdd(&rowsum[row], rs_lo);
            atomicAdd(&rowsum[row + 8], rs_hi);
        }
    }
}

// -------- single-pass stats: lse from accumulated sumexp; JSD + hard CE -----
__global__ __launch_bounds__(256) void stats_kernel() {
    const int row = blockIdx.x;
    const __nv_bfloat16* __restrict__ s = g_LSb + (size_t)row * VOCAB;
    const __nv_bfloat16* __restrict__ t = g_LTb + (size_t)row * VOCAB;
    const int tid = threadIdx.x;
    constexpr int NCHUNK = VOCAB / 8;

    const float lseS = logf(g_seS[row]);
    const float lseT = logf(g_seT[row]);

    float skl = 0.0f, tkl = 0.0f;
    for (int c = tid; c < NCHUNK; c += 256) {
        uint4 vs = *(const uint4*)&s[c * 8];
        uint4 vt = *(const uint4*)&t[c * 8];
        const __nv_bfloat16* es = (const __nv_bfloat16*)&vs;
        const __nv_bfloat16* et = (const __nv_bfloat16*)&vt;
#pragma unroll
        for (int j = 0; j < 8; j++) {
            float lps = __bfloat162float(es[j]) - lseS;
            float lpt = __bfloat162float(et[j]) - lseT;
            float sp = __expf(lps);
            float tp = __expf(lpt);
            float lm = __logf(0.5f * (sp + tp));
            skl += sp * (lps - lm);
            tkl += tp * (lpt - lm);
        }
    }

    __shared__ float shsS[256], shsT[256];
    shsS[tid] = skl;
    shsT[tid] = tkl;
    __syncthreads();
    for (int off = 128; off > 0; off >>= 1) {
        if (tid < off) {
            shsS[tid] += shsS[tid + off];
            shsT[tid] += shsT[tid + off];
        }
        __syncthreads();
    }
    if (tid == 0) {
        atomicAdd(&g_skl, (double)shsS[0]);
        atomicAdd(&g_tkl, (double)shsT[0]);
        int tg = g_tgt[row];
        if (tg != IGNORE_INDEX) {
            float nll = lseS - __bfloat162float(s[tg]);
            atomicAdd(&g_hard, (double)nll);
            atomicAdd(&g_nvalid, 1);
        }
    }
}

// ---------------- finalize ---------------------------------------------------
__global__ void finalize_kernel(float* out) {
    int nv = g_nvalid > 0 ? g_nvalid : 1;
    double hard = g_hard / (double)nv;
    double jsd = 0.5 * (g_skl + g_tkl) / (double)NTOK;
    out[0] = (float)(0.5 * hard + 0.5 * jsd);
}

// ---------------- launch ------------------------------------------------------
extern "C" void kernel_launch(void* const* d_in, const int* in_sizes, int n_in,
                              void* d_out, int out_size) {
    const float* si = (const float*)d_in[0];      // (N, H/2)
    const float* ti = (const float*)d_in[1];      // (N, H)
    const float* sw = (const float*)d_in[2];      // (V, H/2)
    const float* tw = (const float*)d_in[3];      // (V, H)
    const int* tgt_raw = (const int*)d_in[4];     // int32 or int64 (detected)
    float* out = (float*)d_out;

    const int SMEM_BYTES = 3 * 20480;  // 3-stage pipeline, 60KB -> 3 CTAs/SM
    cudaFuncSetAttribute(gemm_kernel,
                         cudaFuncAttributeMaxDynamicSharedMemorySize, SMEM_BYTES);

    // fp32 -> e4m3 (16 elements per thread)
    cvt_fp8_kernel<<<NTOK * KSTU / 16 / 256, 256>>>((const float4*)si, 0, 1.0f);
    cvt_fp8_kernel<<<NTOK * KTEA / 16 / 256, 256>>>((const float4*)ti, 1, 1.0f);
    cvt_fp8_kernel<<<VOCAB * KSTU / 16 / 256, 256>>>((const float4*)sw, 2, WSCALE);
    cvt_fp8_kernel<<<VOCAB * KTEA / 16 / 256, 256>>>((const float4*)tw, 3, WSCALE);

    zero_acc_kernel<<<2, 1024>>>();  // must precede gemm epilogue atomics

    gemm_kernel<<<8000, 256, SMEM_BYTES>>>();  // student [0,4000) + teacher [4000,8000)

    tgt_cvt_kernel<<<1, 1024>>>(tgt_raw);      // before stats
    stats_kernel<<<NTOK, 256>>>();
    finalize_kernel<<<1, 1>>>(out);
}